// round 14
// baseline (speedup 1.0000x reference)
#include <cuda_runtime.h>
#include <cuda_fp16.h>
#include <cstdint>

#define BB 4
#define TT 2048
#define CC 2048
#define FFD 8192
#define BT (BB*TT)          // 8192
#define NCH 64
#define LCH 32

// ---------------- scratch (device globals; no allocation allowed) ----------
__device__ __half g_ek[(size_t)BT*CC];        // exp(k), computed in GEMM epilogue
__device__ __half g_v [(size_t)BT*CC];
__device__ __half g_r [(size_t)BT*CC];
__device__ float g_xmid[(size_t)BT*CC];
__device__ float g_cr  [(size_t)BT*CC];
__device__ float g_Aloc[(size_t)BB*CC*NCH];
__device__ float g_Bloc[(size_t)BB*CC*NCH];
__device__ float g_Sa  [(size_t)BB*CC*NCH];
__device__ float g_Sb  [(size_t)BB*CC*NCH];

// fp16 planes
__device__ __half g_xph[((size_t)BT+1)*CC];   // padded: row0 = 0, row m+1 = xln row m
__device__ __half g_x2h[(size_t)BT*CC];
__device__ __half g_Hh [(size_t)BT*FFD];
__device__ __half g_Wqkv[(size_t)3*CC*CC];    // fused [Wk; Wv; Wr]
__device__ __half g_Wcrh[(size_t)CC*CC];
__device__ __half g_Wckh[(size_t)FFD*CC];
__device__ __half g_Wcvh[(size_t)CC*FFD];

// ======================= PTX helpers (compute_80-safe) ======================
__device__ __forceinline__ uint32_t smem_u32(const void* p) {
    uint32_t a;
    asm("{ .reg .u64 t; cvta.to.shared.u64 t, %1; cvt.u32.u64 %0, t; }" : "=r"(a) : "l"(p));
    return a;
}
__device__ __forceinline__ void cp_async16(uint32_t dst, const void* src) {
    asm volatile("cp.async.cg.shared.global [%0], [%1], 16;" :: "r"(dst), "l"(src) : "memory");
}
__device__ __forceinline__ void cp_commit() {
    asm volatile("cp.async.commit_group;" ::: "memory");
}
template <int N>
__device__ __forceinline__ void cp_wait() {
    asm volatile("cp.async.wait_group %0;" :: "n"(N) : "memory");
}
__device__ __forceinline__ void ldm_x4(uint32_t* r, uint32_t addr) {
    asm volatile("ldmatrix.sync.aligned.m8n8.x4.shared.b16 {%0,%1,%2,%3}, [%4];"
        : "=r"(r[0]), "=r"(r[1]), "=r"(r[2]), "=r"(r[3]) : "r"(addr));
}
__device__ __forceinline__ void mma_f16(float* d, const uint32_t* a, const uint32_t* b) {
    asm volatile(
        "mma.sync.aligned.m16n8k16.row.col.f32.f16.f16.f32 "
        "{%0,%1,%2,%3}, {%4,%5,%6,%7}, {%8,%9}, {%0,%1,%2,%3};"
        : "+f"(d[0]), "+f"(d[1]), "+f"(d[2]), "+f"(d[3])
        : "r"(a[0]), "r"(a[1]), "r"(a[2]), "r"(a[3]), "r"(b[0]), "r"(b[1]));
}
__device__ __forceinline__ uint32_t pkh(__half a, __half b) {
    return (uint32_t)__half_as_ushort(a) | ((uint32_t)__half_as_ushort(b) << 16);
}
// FMA-pipe reciprocal: bit-trick seed + 3 Newton steps (~1e-8 rel err).
__device__ __forceinline__ float fastrcp(float x) {
    float r = __uint_as_float(0x7EF311C3u - __float_as_uint(x));
    r = r * fmaf(-x, r, 2.0f);
    r = r * fmaf(-x, r, 2.0f);
    r = r * fmaf(-x, r, 2.0f);
    return r;
}

// ======================= HMMA GEMM core =====================================
// Y[m0:m0+128, n0:n0+128] = A[128, K] @ W[128, K]^T  (Aptr/Wptr pre-offset).
// fp16 single plane, BK=32, 256 threads, 5-buffer cp.async pipeline with
// PAIRED-STAGE consumption: one cp_wait + one __syncthreads per 2 K-stages.
// Stage s lives in buffer s % NSTAGE. At pair (i, i+1): refill targets are
// buffers of stages i-2, i-1 (consumed last pair, published by entry barrier);
// indices mod 5 {i, i+1, i+3, i+4} are distinct, buffer i+2 holds its prefetch.
// EPI: 0 fp16 | 1 relu^2 fp16 | 2 sigmoid fp32 | 3 out = xadd + xmul*acc | 4 exp fp16
#define ROWB 80u
#define TILEB (128u*ROWB)         // 10240
#define STAGEB (2u*TILEB)         // 20480
#define NSTAGE 5
#define SMEM_BYTES (NSTAGE*STAGEB)  // 102400

template <int EPI>
__device__ __forceinline__ void gemm_core(
    const __half* __restrict__ Aptr, const __half* __restrict__ Wptr,
    float* __restrict__ out, __half* __restrict__ oh,
    const float* __restrict__ xadd, const float* __restrict__ xmul,
    int m0, int n0, int N, int K, char* smem)
{
    const uint32_t sbase = smem_u32(smem);
    const int tid  = threadIdx.x;
    const int lane = tid & 31;
    const int wid  = tid >> 5;
    const int warp_m = wid & 1;
    const int warp_n = wid >> 1;
    const int S = K >> 5;               // even (64 or 256)

    const __half* srcBase[2] = { Aptr, Wptr };

    auto load_stage = [&](int buf, int i) {
        const int k0 = i << 5;
        const uint32_t stage = sbase + buf * STAGEB;
        #pragma unroll
        for (int rep = 0; rep < 4; rep++) {
            const int idx = tid + rep * 256;
            const int tile = idx >> 9;
            const int r = (idx >> 2) & 127;
            const int s = idx & 3;
            const __half* src = srcBase[tile] + (size_t)r * K + k0 + s * 8;
            cp_async16(stage + tile * TILEB + r * ROWB + s * 16, src);
        }
    };

    // prologue: stages 0,1,2 (one commit group per stage)
    #pragma unroll
    for (int p = 0; p < 3; p++) { load_stage(p, p); cp_commit(); }

    float acc[4][4][4];
    #pragma unroll
    for (int mt = 0; mt < 4; mt++)
        #pragma unroll
        for (int nt = 0; nt < 4; nt++)
            #pragma unroll
            for (int q = 0; q < 4; q++) acc[mt][nt][q] = 0.f;

    const uint32_t aoff = (lane & 15) * ROWB + (lane >> 4) * 16;
    const uint32_t boff4 = ((lane >> 4) * 8 + (lane & 7)) * ROWB + ((lane >> 3) & 1) * 16;

    for (int i = 0; i < S; i += 2) {
        cp_wait<1>();            // stages i, i+1 resident (committed through i+2)
        __syncthreads();         // publish cp.async data; protect refill targets
        // refill stages i+3, i+4 (buffers of stages i-2, i-1)
        if (i + 3 < S) load_stage((i + 3) % NSTAGE, i + 3);
        cp_commit();
        if (i + 4 < S) load_stage((i + 4) % NSTAGE, i + 4);
        cp_commit();
        // consume stages i and i+1
        #pragma unroll
        for (int sub = 0; sub < 2; sub++) {
            const uint32_t sb = sbase + ((i + sub) % NSTAGE) * STAGEB;
            #pragma unroll
            for (int ks = 0; ks < 2; ks++) {
                const uint32_t kb = ks * 32;
                uint32_t ahf[4][4];
                #pragma unroll
                for (int mt = 0; mt < 4; mt++)
                    ldm_x4(ahf[mt], sb + (warp_m * 64 + mt * 16) * ROWB + kb + aoff);
                uint32_t bhf[4][2];
                #pragma unroll
                for (int pair = 0; pair < 2; pair++) {
                    uint32_t tmp[4];
                    ldm_x4(tmp, sb + TILEB + (warp_n * 32 + pair * 16) * ROWB + kb + boff4);
                    bhf[pair*2][0] = tmp[0]; bhf[pair*2][1] = tmp[1];
                    bhf[pair*2+1][0] = tmp[2]; bhf[pair*2+1][1] = tmp[3];
                }
                #pragma unroll
                for (int mt = 0; mt < 4; mt++)
                    #pragma unroll
                    for (int nt = 0; nt < 4; nt++)
                        mma_f16(acc[mt][nt], ahf[mt], bhf[nt]);
            }
        }
    }

    const int rbase = m0 + warp_m * 64 + (lane >> 2);
    const int cbase = n0 + warp_n * 32 + (lane & 3) * 2;
    #pragma unroll
    for (int mt = 0; mt < 4; mt++) {
        #pragma unroll
        for (int nt = 0; nt < 4; nt++) {
            const float* c = acc[mt][nt];
            const size_t r0 = (size_t)(rbase + mt * 16);
            const size_t r1 = r0 + 8;
            const int col = cbase + nt * 8;
            if (EPI == 0) {
                *(uint32_t*)&oh[r0 * N + col] = pkh(__float2half_rn(c[0]), __float2half_rn(c[1]));
                *(uint32_t*)&oh[r1 * N + col] = pkh(__float2half_rn(c[2]), __float2half_rn(c[3]));
            } else if (EPI == 4) {
                *(uint32_t*)&oh[r0 * N + col] = pkh(__float2half_rn(__expf(c[0])),
                                                    __float2half_rn(__expf(c[1])));
                *(uint32_t*)&oh[r1 * N + col] = pkh(__float2half_rn(__expf(c[2])),
                                                    __float2half_rn(__expf(c[3])));
            } else if (EPI == 2) {
                *(float2*)&out[r0 * N + col] = make_float2(
                    1.f / (1.f + __expf(-c[0])), 1.f / (1.f + __expf(-c[1])));
                *(float2*)&out[r1 * N + col] = make_float2(
                    1.f / (1.f + __expf(-c[2])), 1.f / (1.f + __expf(-c[3])));
            } else if (EPI == 3) {
                float2 a0 = *(const float2*)&xadd[r0 * N + col];
                float2 m0v = *(const float2*)&xmul[r0 * N + col];
                float2 a1 = *(const float2*)&xadd[r1 * N + col];
                float2 m1v = *(const float2*)&xmul[r1 * N + col];
                *(float2*)&out[r0 * N + col] = make_float2(
                    a0.x + m0v.x * c[0], a0.y + m0v.y * c[1]);
                *(float2*)&out[r1 * N + col] = make_float2(
                    a1.x + m1v.x * c[2], a1.y + m1v.y * c[3]);
            } else {
                float f0 = c[0] > 0.f ? c[0] * c[0] : 0.f;
                float f1 = c[1] > 0.f ? c[1] * c[1] : 0.f;
                float f2 = c[2] > 0.f ? c[2] * c[2] : 0.f;
                float f3 = c[3] > 0.f ? c[3] * c[3] : 0.f;
                *(uint32_t*)&oh[r0 * N + col] = pkh(__float2half_rn(f0), __float2half_rn(f1));
                *(uint32_t*)&oh[r1 * N + col] = pkh(__float2half_rn(f2), __float2half_rn(f3));
            }
        }
    }
}

template <int EPI>
__global__ __launch_bounds__(256, 2) void hmma_gemm(
    const __half* __restrict__ Ah, const __half* __restrict__ Wh,
    float* __restrict__ out, __half* __restrict__ oh,
    const float* __restrict__ xadd, const float* __restrict__ xmul,
    int N, int K)
{
    extern __shared__ char smem[];
    const int m0 = blockIdx.y * 128;
    const int n0 = blockIdx.x * 128;
    gemm_core<EPI>(Ah + (size_t)m0 * K, Wh + (size_t)n0 * K,
                   out, oh, xadd, xmul, m0, n0, N, K, smem);
}

__global__ __launch_bounds__(256, 2) void hmma_gemm_qkv(
    const __half* __restrict__ xph, const __half* __restrict__ Wqkv,
    __half* __restrict__ outek, __half* __restrict__ outv, __half* __restrict__ outr)
{
    extern __shared__ char smem[];
    const int bx = blockIdx.x;
    const int region = bx >> 4;
    const int n0 = (bx & 15) * 128;
    const int m0 = blockIdx.y * 128;
    if (region == 0) {
        gemm_core<4>(xph + (size_t)m0 * CC, Wqkv + (size_t)bx * 128 * CC,
                     0, outek, 0, 0, m0, n0, CC, CC, smem);
    } else {
        const __half* A = (region == 1) ? xph : (xph + CC);
        __half* oh = (region == 1) ? outv : outr;
        gemm_core<0>(A + (size_t)m0 * CC, Wqkv + (size_t)bx * 128 * CC,
                     0, oh, 0, 0, m0, n0, CC, CC, smem);
    }
}

__global__ __launch_bounds__(256, 2) void hmma_gemm_ck(
    const __half* __restrict__ x2h,
    const __half* __restrict__ Wck, const __half* __restrict__ Wcr,
    __half* __restrict__ Hh, float* __restrict__ cr)
{
    extern __shared__ char smem[];
    const int bx = blockIdx.x;
    const int m0 = blockIdx.y * 128;
    if (bx < 64) {
        gemm_core<1>(x2h + (size_t)m0 * CC, Wck + (size_t)bx * 128 * CC,
                     0, Hh, 0, 0, m0, bx * 128, FFD, CC, smem);
    } else {
        gemm_core<2>(x2h + (size_t)m0 * CC, Wcr + (size_t)(bx - 64) * 128 * CC,
                     cr, 0, 0, 0, m0, (bx - 64) * 128, CC, CC, smem);
    }
}

// ======================= layernorm (fp16 plane only) ========================
__device__ __forceinline__ void blockReduce2(float& a, float& b) {
    __shared__ float sa[8], sb[8];
    int lane = threadIdx.x & 31, w = threadIdx.x >> 5;
    #pragma unroll
    for (int o = 16; o > 0; o >>= 1) {
        a += __shfl_down_sync(0xffffffffu, a, o);
        b += __shfl_down_sync(0xffffffffu, b, o);
    }
    if (lane == 0) { sa[w] = a; sb[w] = b; }
    __syncthreads();
    if (w == 0) {
        a = (lane < 8) ? sa[lane] : 0.f;
        b = (lane < 8) ? sb[lane] : 0.f;
        #pragma unroll
        for (int o = 4; o > 0; o >>= 1) {
            a += __shfl_down_sync(0xffffffffu, a, o);
            b += __shfl_down_sync(0xffffffffu, b, o);
        }
        if (lane == 0) { sa[0] = a; sb[0] = b; }
    }
    __syncthreads();
    a = sa[0]; b = sb[0];
    __syncthreads();
}

__global__ __launch_bounds__(256) void ln_kernel(
    const float* __restrict__ x, const float* __restrict__ g,
    const float* __restrict__ bia, __half* __restrict__ yh)
{
    size_t row = blockIdx.x;
    const float* xr = x + row * CC;
    float xv[8];
    float s = 0.f, q = 0.f;
    #pragma unroll
    for (int j = 0; j < 8; j++) {
        xv[j] = xr[threadIdx.x + 256 * j];
        s += xv[j]; q += xv[j] * xv[j];
    }
    blockReduce2(s, q);
    float mu = s * (1.f / CC);
    float var = q * (1.f / CC) - mu * mu;
    float rstd = rsqrtf(var + 1e-5f);
    #pragma unroll
    for (int j = 0; j < 8; j++) {
        int i = threadIdx.x + 256 * j;
        yh[row * CC + i] = __float2half_rn((xv[j] - mu) * rstd * g[i] + bia[i]);
    }
}

__global__ __launch_bounds__(256) void state_ln_kernel(
    const float* __restrict__ x, const float* __restrict__ g,
    const float* __restrict__ bia, float* __restrict__ out)
{
    int b = blockIdx.x;
    const float* xr = x + ((size_t)b * TT + (TT - 2)) * CC;
    float s = 0.f, q = 0.f;
    for (int i = threadIdx.x; i < CC; i += 256) {
        float v = xr[i];
        s += v; q += v * v;
    }
    blockReduce2(s, q);
    float mu = s * (1.f / CC);
    float var = q * (1.f / CC) - mu * mu;
    float rstd = rsqrtf(var + 1e-5f);
    for (int i = threadIdx.x; i < CC; i += 256)
        out[(size_t)b * CC + i] = (xr[i] - mu) * rstd * g[i] + bia[i];
}

// ======================= converters / misc ==================================
__global__ __launch_bounds__(256) void conv_h(
    const float4* __restrict__ src, uint2* __restrict__ hi)
{
    size_t i = (size_t)blockIdx.x * 256 + threadIdx.x;
    float4 f = src[i];
    hi[i] = make_uint2(pkh(__float2half_rn(f.x), __float2half_rn(f.y)),
                       pkh(__float2half_rn(f.z), __float2half_rn(f.w)));
}

__global__ __launch_bounds__(256) void zero1(__half* a)
{
    int i = blockIdx.x * 256 + threadIdx.x;
    a[i] = __float2half_rn(0.f);
}

// ======================= WKV chunked scan (2-wide, ek precomputed) ==========
__global__ __launch_bounds__(256) void wkv_passA(const float* __restrict__ td)
{
    int tid = blockIdx.x * 256 + threadIdx.x;
    int c2 = tid % (CC/2);
    int j  = (tid / (CC/2)) % NCH;
    int b  = tid / ((CC/2) * NCH);
    float2 tdv = *(const float2*)&td[c2 * 2];
    float d0 = __expf(-__expf(tdv.x));
    float d1 = __expf(-__expf(tdv.y));
    float a0 = 0.f, a1 = 0.f, b0 = 0.f, b1 = 0.f;
    size_t base = ((size_t)b * TT + (size_t)j * LCH) * CC + c2 * 2;
    for (int t = 0; t < LCH; t++) {
        float2 ek = __half22float2(*(const __half2*)&g_ek[base + (size_t)t * CC]);
        float2 vv = __half22float2(*(const __half2*)&g_v [base + (size_t)t * CC]);
        if (j == 0 && t == 0) { ek = make_float2(1.f, 1.f); vv = make_float2(0.f, 0.f); }
        a0 = fmaf(d0, a0, ek.x * vv.x);
        a1 = fmaf(d1, a1, ek.y * vv.y);
        b0 = fmaf(d0, b0, ek.x);
        b1 = fmaf(d1, b1, ek.y);
    }
    size_t idx = ((size_t)b * NCH + j) * CC + c2 * 2;
    *(float2*)&g_Aloc[idx] = make_float2(a0, a1);
    *(float2*)&g_Bloc[idx] = make_float2(b0, b1);
}

__global__ __launch_bounds__(256) void wkv_passB(const float* __restrict__ td)
{
    int tid = blockIdx.x * 256 + threadIdx.x;
    int c = tid % CC;
    int b = tid / CC;
    float dL = __expf(-(float)LCH * __expf(td[c]));
    float sa = 0.f, sb = 0.f;
    for (int j = 0; j < NCH; j++) {
        size_t idx = ((size_t)b * NCH + j) * CC + c;
        g_Sa[idx] = sa;
        g_Sb[idx] = sb;
        sa = dL * sa + g_Aloc[idx];
        sb = dL * sb + g_Bloc[idx];
    }
}

__global__ __launch_bounds__(256) void wkv_passC(
    const float* __restrict__ td, const float* __restrict__ x)
{
    int tid = blockIdx.x * 256 + threadIdx.x;
    int c2 = tid % (CC/2);
    int j  = (tid / (CC/2)) % NCH;
    int b  = tid / ((CC/2) * NCH);
    float2 tdv = *(const float2*)&td[c2 * 2];
    float d0 = __expf(-__expf(tdv.x));
    float d1 = __expf(-__expf(tdv.y));
    size_t idx = ((size_t)b * NCH + j) * CC + c2 * 2;
    float2 sa = *(const float2*)&g_Sa[idx];
    float2 sb = *(const float2*)&g_Sb[idx];
    float a0 = sa.x, a1 = sa.y, b0 = sb.x, b1 = sb.y;
    size_t base = ((size_t)b * TT + (size_t)j * LCH) * CC + c2 * 2;
    for (int t = 0; t < LCH; t++) {
        size_t p = base + (size_t)t * CC;
        float2 ek = __half22float2(*(const __half2*)&g_ek[p]);
        float2 vv = __half22float2(*(const __half2*)&g_v [p]);
        if (j == 0 && t == 0) { ek = make_float2(1.f, 1.f); vv = make_float2(0.f, 0.f); }
        a0 = fmaf(d0, a0, ek.x * vv.x);
        a1 = fmaf(d1, a1, ek.y * vv.y);
        b0 = fmaf(d0, b0, ek.x);
        b1 = fmaf(d1, b1, ek.y);
        float2 rr = __half22float2(*(const __half2*)&g_r[p]);
        float2 xx = *(const float2*)&x[p];
        float w0 = a0 * fastrcp(b0 + 1e-8f);
        float w1 = a1 * fastrcp(b1 + 1e-8f);
        *(float2*)&g_xmid[p] = make_float2(fmaf(rr.x, w0, xx.x), fmaf(rr.y, w1, xx.y));
    }
}

// ======================= host launch =========================================
extern "C" void kernel_launch(void* const* d_in, const int* in_sizes, int n_in,
                              void* d_out, int out_size)
{
    const float* x     = (const float*)d_in[0];
    const float* ln1_g = (const float*)d_in[1];
    const float* ln1_b = (const float*)d_in[2];
    const float* td    = (const float*)d_in[3];
    const float* Wk    = (const float*)d_in[4];
    const float* Wv    = (const float*)d_in[5];
    const float* Wr    = (const float*)d_in[6];
    const float* ln2_g = (const float*)d_in[7];
    const float* ln2_b = (const float*)d_in[8];
    const float* Wck   = (const float*)d_in[9];
    const float* Wcv   = (const float*)d_in[10];
    const float* Wcr   = (const float*)d_in[11];
    float* out = (float*)d_out;

    float *p_xmid, *p_cr;
    __half *p_ek, *p_v, *p_r;
    __half *p_xph, *p_x2h, *p_Hh, *p_Wqkv, *p_Wcrh, *p_Wckh, *p_Wcvh;
    cudaGetSymbolAddress((void**)&p_ek,   g_ek);
    cudaGetSymbolAddress((void**)&p_v,    g_v);
    cudaGetSymbolAddress((void**)&p_r,    g_r);
    cudaGetSymbolAddress((void**)&p_xmid, g_xmid);
    cudaGetSymbolAddress((void**)&p_cr,   g_cr);
    cudaGetSymbolAddress((void**)&p_xph,  g_xph);
    cudaGetSymbolAddress((void**)&p_x2h,  g_x2h);
    cudaGetSymbolAddress((void**)&p_Hh,   g_Hh);
    cudaGetSymbolAddress((void**)&p_Wqkv, g_Wqkv);
    cudaGetSymbolAddress((void**)&p_Wcrh, g_Wcrh);
    cudaGetSymbolAddress((void**)&p_Wckh, g_Wckh);
    cudaGetSymbolAddress((void**)&p_Wcvh, g_Wcvh);

    cudaFuncSetAttribute(hmma_gemm<3>,  cudaFuncAttributeMaxDynamicSharedMemorySize, SMEM_BYTES);
    cudaFuncSetAttribute(hmma_gemm_qkv, cudaFuncAttributeMaxDynamicSharedMemorySize, SMEM_BYTES);
    cudaFuncSetAttribute(hmma_gemm_ck,  cudaFuncAttributeMaxDynamicSharedMemorySize, SMEM_BYTES);

    // fork-join side streams (created once; host-side objects, no device memory)
    static cudaStream_t s1 = nullptr, s2 = nullptr;
    static cudaEvent_t evRoot = nullptr, evQKVW = nullptr, evW2 = nullptr;
    if (!s1) {
        cudaStreamCreateWithFlags(&s1, cudaStreamNonBlocking);
        cudaStreamCreateWithFlags(&s2, cudaStreamNonBlocking);
        cudaEventCreateWithFlags(&evRoot, cudaEventDisableTiming);
        cudaEventCreateWithFlags(&evQKVW, cudaEventDisableTiming);
        cudaEventCreateWithFlags(&evW2,   cudaEventDisableTiming);
    }

    // ---- fork ----
    cudaEventRecord(evRoot, 0);
    cudaStreamWaitEvent(s1, evRoot, 0);
    cudaStreamWaitEvent(s2, evRoot, 0);

    // s1: qkv weight conversion (parallel with LN1/zero on s0)
    conv_h<<<(CC*CC)/1024, 256, 0, s1>>>((const float4*)Wk, (uint2*)p_Wqkv);
    conv_h<<<(CC*CC)/1024, 256, 0, s1>>>((const float4*)Wv, (uint2*)(p_Wqkv + (size_t)CC*CC));
    conv_h<<<(CC*CC)/1024, 256, 0, s1>>>((const float4*)Wr, (uint2*)(p_Wqkv + (size_t)2*CC*CC));
    cudaEventRecord(evQKVW, s1);

    // s2: channel-mix weight conversions + state output (parallel with qkv GEMM on s0)
    conv_h<<<(CC*CC)/1024,  256, 0, s2>>>((const float4*)Wcr, (uint2*)p_Wcrh);
    conv_h<<<(FFD*CC)/1024, 256, 0, s2>>>((const float4*)Wck, (uint2*)p_Wckh);
    conv_h<<<(CC*FFD)/1024, 256, 0, s2>>>((const float4*)Wcv, (uint2*)p_Wcvh);
    if ((size_t)out_size >= (size_t)BT * CC + (size_t)BB * CC)
        state_ln_kernel<<<BB, 256, 0, s2>>>(x, ln1_g, ln1_b, out + (size_t)BT * CC);
    cudaEventRecord(evW2, s2);

    // s0: LN1 -> padded fp16 plane (row m at plane row m+1), zero row 0
    ln_kernel<<<BT, 256>>>(x, ln1_g, ln1_b, p_xph + CC);
    zero1<<<CC/256, 256>>>(p_xph);

    // join s1, then fused k/v/r GEMM (k region stores exp(k))
    cudaStreamWaitEvent(0, evQKVW, 0);
    hmma_gemm_qkv<<<dim3(48, BT / 128), 256, SMEM_BYTES>>>(p_xph, p_Wqkv, p_ek, p_v, p_r);

    // WKV scan + residual -> xmid (2-wide kernels)
    wkv_passA<<<(BB * NCH * CC / 2) / 256, 256>>>(td);
    wkv_passB<<<(BB * CC) / 256, 256>>>(td);
    wkv_passC<<<(BB * NCH * CC / 2) / 256, 256>>>(td, x);

    // LN2 -> x2 fp16 plane
    ln_kernel<<<BT, 256>>>(p_xmid, ln2_g, ln2_b, p_x2h);

    // join s2, then fused channel-mix: Wck (relu^2 -> Hh) + Wcr (sigmoid -> cr)
    cudaStreamWaitEvent(0, evW2, 0);
    hmma_gemm_ck<<<dim3(80, BT / 128), 256, SMEM_BYTES>>>(p_x2h, p_Wckh, p_Wcrh, p_Hh, p_cr);

    // dv GEMM with fused final epilogue: out = xmid + cr * dv
    hmma_gemm<3><<<dim3(CC / 128, BT / 128), 256, SMEM_BYTES>>>(
        p_Hh, p_Wcvh, out, 0, p_xmid, p_cr, CC, FFD);
}

// round 15
// speedup vs baseline: 1.1374x; 1.1374x over previous
#include <cuda_runtime.h>
#include <cuda_fp16.h>
#include <cstdint>

#define BB 4
#define TT 2048
#define CC 2048
#define FFD 8192
#define BT (BB*TT)          // 8192
#define NCH 64
#define LCH 32

// ---------------- scratch (device globals; no allocation allowed) ----------
__device__ __half g_ek[(size_t)BT*CC];        // exp(k), computed in GEMM epilogue
__device__ __half g_v [(size_t)BT*CC];
__device__ __half g_r [(size_t)BT*CC];
__device__ float g_xmid[(size_t)BT*CC];
__device__ __half g_cr [(size_t)BT*CC];       // sigmoid output, fp16
__device__ float g_Aloc[(size_t)BB*CC*NCH];
__device__ float g_Bloc[(size_t)BB*CC*NCH];
__device__ float g_Sa  [(size_t)BB*CC*NCH];
__device__ float g_Sb  [(size_t)BB*CC*NCH];

// fp16 planes
__device__ __half g_xph[((size_t)BT+1)*CC];   // padded: row0 = 0, row m+1 = xln row m
__device__ __half g_x2h[(size_t)BT*CC];
__device__ __half g_Hh [(size_t)BT*FFD];
__device__ __half g_Wqkv[(size_t)3*CC*CC];    // fused [Wk; Wv; Wr]
__device__ __half g_Wcrh[(size_t)CC*CC];
__device__ __half g_Wckh[(size_t)FFD*CC];
__device__ __half g_Wcvh[(size_t)CC*FFD];

// ======================= PTX helpers (compute_80-safe) ======================
__device__ __forceinline__ uint32_t smem_u32(const void* p) {
    uint32_t a;
    asm("{ .reg .u64 t; cvta.to.shared.u64 t, %1; cvt.u32.u64 %0, t; }" : "=r"(a) : "l"(p));
    return a;
}
__device__ __forceinline__ void cp_async16(uint32_t dst, const void* src) {
    asm volatile("cp.async.cg.shared.global [%0], [%1], 16;" :: "r"(dst), "l"(src) : "memory");
}
__device__ __forceinline__ void cp_commit() {
    asm volatile("cp.async.commit_group;" ::: "memory");
}
template <int N>
__device__ __forceinline__ void cp_wait() {
    asm volatile("cp.async.wait_group %0;" :: "n"(N) : "memory");
}
__device__ __forceinline__ void ldm_x4(uint32_t* r, uint32_t addr) {
    asm volatile("ldmatrix.sync.aligned.m8n8.x4.shared.b16 {%0,%1,%2,%3}, [%4];"
        : "=r"(r[0]), "=r"(r[1]), "=r"(r[2]), "=r"(r[3]) : "r"(addr));
}
__device__ __forceinline__ void mma_f16(float* d, const uint32_t* a, const uint32_t* b) {
    asm volatile(
        "mma.sync.aligned.m16n8k16.row.col.f32.f16.f16.f32 "
        "{%0,%1,%2,%3}, {%4,%5,%6,%7}, {%8,%9}, {%0,%1,%2,%3};"
        : "+f"(d[0]), "+f"(d[1]), "+f"(d[2]), "+f"(d[3])
        : "r"(a[0]), "r"(a[1]), "r"(a[2]), "r"(a[3]), "r"(b[0]), "r"(b[1]));
}
__device__ __forceinline__ uint32_t pkh(__half a, __half b) {
    return (uint32_t)__half_as_ushort(a) | ((uint32_t)__half_as_ushort(b) << 16);
}
// FMA-pipe reciprocal: bit-trick seed + 3 Newton steps (~1e-8 rel err).
__device__ __forceinline__ float fastrcp(float x) {
    float r = __uint_as_float(0x7EF311C3u - __float_as_uint(x));
    r = r * fmaf(-x, r, 2.0f);
    r = r * fmaf(-x, r, 2.0f);
    r = r * fmaf(-x, r, 2.0f);
    return r;
}

// ======================= HMMA GEMM core (round-13 mainloop) ==================
// Y[m0:m0+128, n0:n0+128] = A[128, K] @ W[128, K]^T  (Aptr/Wptr pre-offset).
// fp16 single plane, BK=32, 256 threads, 5-stage cp.async pipeline, 2 CTA/SM.
// Stage s lives in buffer s % NSTAGE; one cp_wait<NSTAGE-2> + barrier per stage.
// EPI: 0 fp16 | 1 relu^2 fp16 | 2 sigmoid fp16 | 3 out = xadd + xmul*acc | 4 exp fp16
#define ROWB 80u
#define TILEB (128u*ROWB)         // 10240
#define STAGEB (2u*TILEB)         // 20480
#define NSTAGE 5
#define SMEM_BYTES (NSTAGE*STAGEB)  // 102400

template <int EPI>
__device__ __forceinline__ void gemm_core(
    const __half* __restrict__ Aptr, const __half* __restrict__ Wptr,
    float* __restrict__ out, __half* __restrict__ oh,
    const float* __restrict__ xadd, const __half* __restrict__ xmul,
    int m0, int n0, int N, int K, char* smem)
{
    const uint32_t sbase = smem_u32(smem);
    const int tid  = threadIdx.x;
    const int lane = tid & 31;
    const int wid  = tid >> 5;
    const int warp_m = wid & 1;
    const int warp_n = wid >> 1;
    const int S = K >> 5;

    const __half* srcBase[2] = { Aptr, Wptr };

    auto load_stage = [&](int buf, int i) {
        const int k0 = i << 5;
        const uint32_t stage = sbase + buf * STAGEB;
        #pragma unroll
        for (int rep = 0; rep < 4; rep++) {
            const int idx = tid + rep * 256;
            const int tile = idx >> 9;
            const int r = (idx >> 2) & 127;
            const int s = idx & 3;
            const __half* src = srcBase[tile] + (size_t)r * K + k0 + s * 8;
            cp_async16(stage + tile * TILEB + r * ROWB + s * 16, src);
        }
    };

    #pragma unroll
    for (int p = 0; p < NSTAGE - 1; p++) { load_stage(p, p); cp_commit(); }

    float acc[4][4][4];
    #pragma unroll
    for (int mt = 0; mt < 4; mt++)
        #pragma unroll
        for (int nt = 0; nt < 4; nt++)
            #pragma unroll
            for (int q = 0; q < 4; q++) acc[mt][nt][q] = 0.f;

    const uint32_t aoff = (lane & 15) * ROWB + (lane >> 4) * 16;
    const uint32_t boff4 = ((lane >> 4) * 8 + (lane & 7)) * ROWB + ((lane >> 3) & 1) * 16;

    for (int i = 0; i < S; i++) {
        cp_wait<NSTAGE - 2>();
        __syncthreads();
        const uint32_t sb = sbase + (i % NSTAGE) * STAGEB;
        #pragma unroll
        for (int ks = 0; ks < 2; ks++) {
            const uint32_t kb = ks * 32;
            uint32_t ahf[4][4];
            #pragma unroll
            for (int mt = 0; mt < 4; mt++)
                ldm_x4(ahf[mt], sb + (warp_m * 64 + mt * 16) * ROWB + kb + aoff);
            uint32_t bhf[4][2];
            #pragma unroll
            for (int pair = 0; pair < 2; pair++) {
                uint32_t tmp[4];
                ldm_x4(tmp, sb + TILEB + (warp_n * 32 + pair * 16) * ROWB + kb + boff4);
                bhf[pair*2][0] = tmp[0]; bhf[pair*2][1] = tmp[1];
                bhf[pair*2+1][0] = tmp[2]; bhf[pair*2+1][1] = tmp[3];
            }
            #pragma unroll
            for (int mt = 0; mt < 4; mt++)
                #pragma unroll
                for (int nt = 0; nt < 4; nt++)
                    mma_f16(acc[mt][nt], ahf[mt], bhf[nt]);
        }
        if (i + NSTAGE - 1 < S) load_stage((i + NSTAGE - 1) % NSTAGE, i + NSTAGE - 1);
        cp_commit();
    }

    const int rbase = m0 + warp_m * 64 + (lane >> 2);
    const int cbase = n0 + warp_n * 32 + (lane & 3) * 2;
    #pragma unroll
    for (int mt = 0; mt < 4; mt++) {
        #pragma unroll
        for (int nt = 0; nt < 4; nt++) {
            const float* c = acc[mt][nt];
            const size_t r0 = (size_t)(rbase + mt * 16);
            const size_t r1 = r0 + 8;
            const int col = cbase + nt * 8;
            if (EPI == 0) {
                *(uint32_t*)&oh[r0 * N + col] = pkh(__float2half_rn(c[0]), __float2half_rn(c[1]));
                *(uint32_t*)&oh[r1 * N + col] = pkh(__float2half_rn(c[2]), __float2half_rn(c[3]));
            } else if (EPI == 4) {
                *(uint32_t*)&oh[r0 * N + col] = pkh(__float2half_rn(__expf(c[0])),
                                                    __float2half_rn(__expf(c[1])));
                *(uint32_t*)&oh[r1 * N + col] = pkh(__float2half_rn(__expf(c[2])),
                                                    __float2half_rn(__expf(c[3])));
            } else if (EPI == 2) {   // sigmoid -> fp16
                *(uint32_t*)&oh[r0 * N + col] = pkh(
                    __float2half_rn(1.f / (1.f + __expf(-c[0]))),
                    __float2half_rn(1.f / (1.f + __expf(-c[1]))));
                *(uint32_t*)&oh[r1 * N + col] = pkh(
                    __float2half_rn(1.f / (1.f + __expf(-c[2]))),
                    __float2half_rn(1.f / (1.f + __expf(-c[3]))));
            } else if (EPI == 3) {   // out = xadd + xmul(half) * acc
                float2 a0 = *(const float2*)&xadd[r0 * N + col];
                float2 m0v = __half22float2(*(const __half2*)&xmul[r0 * N + col]);
                float2 a1 = *(const float2*)&xadd[r1 * N + col];
                float2 m1v = __half22float2(*(const __half2*)&xmul[r1 * N + col]);
                *(float2*)&out[r0 * N + col] = make_float2(
                    fmaf(m0v.x, c[0], a0.x), fmaf(m0v.y, c[1], a0.y));
                *(float2*)&out[r1 * N + col] = make_float2(
                    fmaf(m1v.x, c[2], a1.x), fmaf(m1v.y, c[3], a1.y));
            } else {   // EPI == 1: relu^2 -> fp16
                float f0 = c[0] > 0.f ? c[0] * c[0] : 0.f;
                float f1 = c[1] > 0.f ? c[1] * c[1] : 0.f;
                float f2 = c[2] > 0.f ? c[2] * c[2] : 0.f;
                float f3 = c[3] > 0.f ? c[3] * c[3] : 0.f;
                *(uint32_t*)&oh[r0 * N + col] = pkh(__float2half_rn(f0), __float2half_rn(f1));
                *(uint32_t*)&oh[r1 * N + col] = pkh(__float2half_rn(f2), __float2half_rn(f3));
            }
        }
    }
}

template <int EPI>
__global__ __launch_bounds__(256, 2) void hmma_gemm(
    const __half* __restrict__ Ah, const __half* __restrict__ Wh,
    float* __restrict__ out, __half* __restrict__ oh,
    const float* __restrict__ xadd, const __half* __restrict__ xmul,
    int N, int K)
{
    extern __shared__ char smem[];
    const int m0 = blockIdx.y * 128;
    const int n0 = blockIdx.x * 128;
    gemm_core<EPI>(Ah + (size_t)m0 * K, Wh + (size_t)n0 * K,
                   out, oh, xadd, xmul, m0, n0, N, K, smem);
}

__global__ __launch_bounds__(256, 2) void hmma_gemm_qkv(
    const __half* __restrict__ xph, const __half* __restrict__ Wqkv,
    __half* __restrict__ outek, __half* __restrict__ outv, __half* __restrict__ outr)
{
    extern __shared__ char smem[];
    const int bx = blockIdx.x;
    const int region = bx >> 4;
    const int n0 = (bx & 15) * 128;
    const int m0 = blockIdx.y * 128;
    if (region == 0) {
        gemm_core<4>(xph + (size_t)m0 * CC, Wqkv + (size_t)bx * 128 * CC,
                     0, outek, 0, 0, m0, n0, CC, CC, smem);
    } else {
        const __half* A = (region == 1) ? xph : (xph + CC);
        __half* oh = (region == 1) ? outv : outr;
        gemm_core<0>(A + (size_t)m0 * CC, Wqkv + (size_t)bx * 128 * CC,
                     0, oh, 0, 0, m0, n0, CC, CC, smem);
    }
}

__global__ __launch_bounds__(256, 2) void hmma_gemm_ck(
    const __half* __restrict__ x2h,
    const __half* __restrict__ Wck, const __half* __restrict__ Wcr,
    __half* __restrict__ Hh, __half* __restrict__ cr)
{
    extern __shared__ char smem[];
    const int bx = blockIdx.x;
    const int m0 = blockIdx.y * 128;
    if (bx < 64) {
        gemm_core<1>(x2h + (size_t)m0 * CC, Wck + (size_t)bx * 128 * CC,
                     0, Hh, 0, 0, m0, bx * 128, FFD, CC, smem);
    } else {
        gemm_core<2>(x2h + (size_t)m0 * CC, Wcr + (size_t)(bx - 64) * 128 * CC,
                     0, cr, 0, 0, m0, (bx - 64) * 128, CC, CC, smem);
    }
}

// ======================= layernorm (fp16 plane only) ========================
__device__ __forceinline__ void blockReduce2(float& a, float& b) {
    __shared__ float sa[8], sb[8];
    int lane = threadIdx.x & 31, w = threadIdx.x >> 5;
    #pragma unroll
    for (int o = 16; o > 0; o >>= 1) {
        a += __shfl_down_sync(0xffffffffu, a, o);
        b += __shfl_down_sync(0xffffffffu, b, o);
    }
    if (lane == 0) { sa[w] = a; sb[w] = b; }
    __syncthreads();
    if (w == 0) {
        a = (lane < 8) ? sa[lane] : 0.f;
        b = (lane < 8) ? sb[lane] : 0.f;
        #pragma unroll
        for (int o = 4; o > 0; o >>= 1) {
            a += __shfl_down_sync(0xffffffffu, a, o);
            b += __shfl_down_sync(0xffffffffu, b, o);
        }
        if (lane == 0) { sa[0] = a; sb[0] = b; }
    }
    __syncthreads();
    a = sa[0]; b = sb[0];
    __syncthreads();
}

__global__ __launch_bounds__(256) void ln_kernel(
    const float* __restrict__ x, const float* __restrict__ g,
    const float* __restrict__ bia, __half* __restrict__ yh)
{
    size_t row = blockIdx.x;
    const float* xr = x + row * CC;
    float xv[8];
    float s = 0.f, q = 0.f;
    #pragma unroll
    for (int j = 0; j < 8; j++) {
        xv[j] = xr[threadIdx.x + 256 * j];
        s += xv[j]; q += xv[j] * xv[j];
    }
    blockReduce2(s, q);
    float mu = s * (1.f / CC);
    float var = q * (1.f / CC) - mu * mu;
    float rstd = rsqrtf(var + 1e-5f);
    #pragma unroll
    for (int j = 0; j < 8; j++) {
        int i = threadIdx.x + 256 * j;
        yh[row * CC + i] = __float2half_rn((xv[j] - mu) * rstd * g[i] + bia[i]);
    }
}

__global__ __launch_bounds__(256) void state_ln_kernel(
    const float* __restrict__ x, const float* __restrict__ g,
    const float* __restrict__ bia, float* __restrict__ out)
{
    int b = blockIdx.x;
    const float* xr = x + ((size_t)b * TT + (TT - 2)) * CC;
    float s = 0.f, q = 0.f;
    for (int i = threadIdx.x; i < CC; i += 256) {
        float v = xr[i];
        s += v; q += v * v;
    }
    blockReduce2(s, q);
    float mu = s * (1.f / CC);
    float var = q * (1.f / CC) - mu * mu;
    float rstd = rsqrtf(var + 1e-5f);
    for (int i = threadIdx.x; i < CC; i += 256)
        out[(size_t)b * CC + i] = (xr[i] - mu) * rstd * g[i] + bia[i];
}

// ======================= converters / misc ==================================
__global__ __launch_bounds__(256) void conv_h(
    const float4* __restrict__ src, uint2* __restrict__ hi)
{
    size_t i = (size_t)blockIdx.x * 256 + threadIdx.x;
    float4 f = src[i];
    hi[i] = make_uint2(pkh(__float2half_rn(f.x), __float2half_rn(f.y)),
                       pkh(__float2half_rn(f.z), __float2half_rn(f.w)));
}

__global__ __launch_bounds__(256) void zero1(__half* a)
{
    int i = blockIdx.x * 256 + threadIdx.x;
    a[i] = __float2half_rn(0.f);
}

// ======================= WKV chunked scan (2-wide, ek precomputed) ==========
__global__ __launch_bounds__(256) void wkv_passA(const float* __restrict__ td)
{
    int tid = blockIdx.x * 256 + threadIdx.x;
    int c2 = tid % (CC/2);
    int j  = (tid / (CC/2)) % NCH;
    int b  = tid / ((CC/2) * NCH);
    float2 tdv = *(const float2*)&td[c2 * 2];
    float d0 = __expf(-__expf(tdv.x));
    float d1 = __expf(-__expf(tdv.y));
    float a0 = 0.f, a1 = 0.f, b0 = 0.f, b1 = 0.f;
    size_t base = ((size_t)b * TT + (size_t)j * LCH) * CC + c2 * 2;
    for (int t = 0; t < LCH; t++) {
        float2 ek = __half22float2(*(const __half2*)&g_ek[base + (size_t)t * CC]);
        float2 vv = __half22float2(*(const __half2*)&g_v [base + (size_t)t * CC]);
        if (j == 0 && t == 0) { ek = make_float2(1.f, 1.f); vv = make_float2(0.f, 0.f); }
        a0 = fmaf(d0, a0, ek.x * vv.x);
        a1 = fmaf(d1, a1, ek.y * vv.y);
        b0 = fmaf(d0, b0, ek.x);
        b1 = fmaf(d1, b1, ek.y);
    }
    size_t idx = ((size_t)b * NCH + j) * CC + c2 * 2;
    *(float2*)&g_Aloc[idx] = make_float2(a0, a1);
    *(float2*)&g_Bloc[idx] = make_float2(b0, b1);
}

__global__ __launch_bounds__(256) void wkv_passB(const float* __restrict__ td)
{
    int tid = blockIdx.x * 256 + threadIdx.x;    // BB*CC/2 threads
    int c2 = tid % (CC/2);
    int b  = tid / (CC/2);
    float2 tdv = *(const float2*)&td[c2 * 2];
    float dL0 = __expf(-(float)LCH * __expf(tdv.x));
    float dL1 = __expf(-(float)LCH * __expf(tdv.y));
    float sa0 = 0.f, sa1 = 0.f, sb0 = 0.f, sb1 = 0.f;
    for (int j = 0; j < NCH; j++) {
        size_t idx = ((size_t)b * NCH + j) * CC + c2 * 2;
        *(float2*)&g_Sa[idx] = make_float2(sa0, sa1);
        *(float2*)&g_Sb[idx] = make_float2(sb0, sb1);
        float2 al = *(const float2*)&g_Aloc[idx];
        float2 bl = *(const float2*)&g_Bloc[idx];
        sa0 = fmaf(dL0, sa0, al.x);
        sa1 = fmaf(dL1, sa1, al.y);
        sb0 = fmaf(dL0, sb0, bl.x);
        sb1 = fmaf(dL1, sb1, bl.y);
    }
}

__global__ __launch_bounds__(256) void wkv_passC(
    const float* __restrict__ td, const float* __restrict__ x)
{
    int tid = blockIdx.x * 256 + threadIdx.x;
    int c2 = tid % (CC/2);
    int j  = (tid / (CC/2)) % NCH;
    int b  = tid / ((CC/2) * NCH);
    float2 tdv = *(const float2*)&td[c2 * 2];
    float d0 = __expf(-__expf(tdv.x));
    float d1 = __expf(-__expf(tdv.y));
    size_t idx = ((size_t)b * NCH + j) * CC + c2 * 2;
    float2 sa = *(const float2*)&g_Sa[idx];
    float2 sb = *(const float2*)&g_Sb[idx];
    float a0 = sa.x, a1 = sa.y, b0 = sb.x, b1 = sb.y;
    size_t base = ((size_t)b * TT + (size_t)j * LCH) * CC + c2 * 2;
    for (int t = 0; t < LCH; t++) {
        size_t p = base + (size_t)t * CC;
        float2 ek = __half22float2(*(const __half2*)&g_ek[p]);
        float2 vv = __half22float2(*(const __half2*)&g_v [p]);
        if (j == 0 && t == 0) { ek = make_float2(1.f, 1.f); vv = make_float2(0.f, 0.f); }
        a0 = fmaf(d0, a0, ek.x * vv.x);
        a1 = fmaf(d1, a1, ek.y * vv.y);
        b0 = fmaf(d0, b0, ek.x);
        b1 = fmaf(d1, b1, ek.y);
        float2 rr = __half22float2(*(const __half2*)&g_r[p]);
        float2 xx = *(const float2*)&x[p];
        float w0 = a0 * fastrcp(b0 + 1e-8f);
        float w1 = a1 * fastrcp(b1 + 1e-8f);
        *(float2*)&g_xmid[p] = make_float2(fmaf(rr.x, w0, xx.x), fmaf(rr.y, w1, xx.y));
    }
}

// ======================= host launch =========================================
extern "C" void kernel_launch(void* const* d_in, const int* in_sizes, int n_in,
                              void* d_out, int out_size)
{
    const float* x     = (const float*)d_in[0];
    const float* ln1_g = (const float*)d_in[1];
    const float* ln1_b = (const float*)d_in[2];
    const float* td    = (const float*)d_in[3];
    const float* Wk    = (const float*)d_in[4];
    const float* Wv    = (const float*)d_in[5];
    const float* Wr    = (const float*)d_in[6];
    const float* ln2_g = (const float*)d_in[7];
    const float* ln2_b = (const float*)d_in[8];
    const float* Wck   = (const float*)d_in[9];
    const float* Wcv   = (const float*)d_in[10];
    const float* Wcr   = (const float*)d_in[11];
    float* out = (float*)d_out;

    float *p_xmid;
    __half *p_ek, *p_v, *p_r, *p_cr;
    __half *p_xph, *p_x2h, *p_Hh, *p_Wqkv, *p_Wcrh, *p_Wckh, *p_Wcvh;
    cudaGetSymbolAddress((void**)&p_ek,   g_ek);
    cudaGetSymbolAddress((void**)&p_v,    g_v);
    cudaGetSymbolAddress((void**)&p_r,    g_r);
    cudaGetSymbolAddress((void**)&p_xmid, g_xmid);
    cudaGetSymbolAddress((void**)&p_cr,   g_cr);
    cudaGetSymbolAddress((void**)&p_xph,  g_xph);
    cudaGetSymbolAddress((void**)&p_x2h,  g_x2h);
    cudaGetSymbolAddress((void**)&p_Hh,   g_Hh);
    cudaGetSymbolAddress((void**)&p_Wqkv, g_Wqkv);
    cudaGetSymbolAddress((void**)&p_Wcrh, g_Wcrh);
    cudaGetSymbolAddress((void**)&p_Wckh, g_Wckh);
    cudaGetSymbolAddress((void**)&p_Wcvh, g_Wcvh);

    cudaFuncSetAttribute(hmma_gemm<3>,  cudaFuncAttributeMaxDynamicSharedMemorySize, SMEM_BYTES);
    cudaFuncSetAttribute(hmma_gemm_qkv, cudaFuncAttributeMaxDynamicSharedMemorySize, SMEM_BYTES);
    cudaFuncSetAttribute(hmma_gemm_ck,  cudaFuncAttributeMaxDynamicSharedMemorySize, SMEM_BYTES);

    // fork-join side streams (created once; host-side objects, no device memory)
    static cudaStream_t s1 = nullptr, s2 = nullptr;
    static cudaEvent_t evRoot = nullptr, evQKVW = nullptr, evW2 = nullptr;
    if (!s1) {
        cudaStreamCreateWithFlags(&s1, cudaStreamNonBlocking);
        cudaStreamCreateWithFlags(&s2, cudaStreamNonBlocking);
        cudaEventCreateWithFlags(&evRoot, cudaEventDisableTiming);
        cudaEventCreateWithFlags(&evQKVW, cudaEventDisableTiming);
        cudaEventCreateWithFlags(&evW2,   cudaEventDisableTiming);
    }

    // ---- fork ----
    cudaEventRecord(evRoot, 0);
    cudaStreamWaitEvent(s1, evRoot, 0);
    cudaStreamWaitEvent(s2, evRoot, 0);

    // s1: qkv weight conversion (parallel with LN1/zero on s0)
    conv_h<<<(CC*CC)/1024, 256, 0, s1>>>((const float4*)Wk, (uint2*)p_Wqkv);
    conv_h<<<(CC*CC)/1024, 256, 0, s1>>>((const float4*)Wv, (uint2*)(p_Wqkv + (size_t)CC*CC));
    conv_h<<<(CC*CC)/1024, 256, 0, s1>>>((const float4*)Wr, (uint2*)(p_Wqkv + (size_t)2*CC*CC));
    cudaEventRecord(evQKVW, s1);

    // s2: channel-mix weight conversions + state output (parallel with qkv GEMM on s0)
    conv_h<<<(CC*CC)/1024,  256, 0, s2>>>((const float4*)Wcr, (uint2*)p_Wcrh);
    conv_h<<<(FFD*CC)/1024, 256, 0, s2>>>((const float4*)Wck, (uint2*)p_Wckh);
    conv_h<<<(CC*FFD)/1024, 256, 0, s2>>>((const float4*)Wcv, (uint2*)p_Wcvh);
    if ((size_t)out_size >= (size_t)BT * CC + (size_t)BB * CC)
        state_ln_kernel<<<BB, 256, 0, s2>>>(x, ln1_g, ln1_b, out + (size_t)BT * CC);
    cudaEventRecord(evW2, s2);

    // s0: LN1 -> padded fp16 plane (row m at plane row m+1), zero row 0
    ln_kernel<<<BT, 256>>>(x, ln1_g, ln1_b, p_xph + CC);
    zero1<<<CC/256, 256>>>(p_xph);

    // join s1, then fused k/v/r GEMM (k region stores exp(k))
    cudaStreamWaitEvent(0, evQKVW, 0);
    hmma_gemm_qkv<<<dim3(48, BT / 128), 256, SMEM_BYTES>>>(p_xph, p_Wqkv, p_ek, p_v, p_r);

    // WKV scan + residual -> xmid (2-wide kernels)
    wkv_passA<<<(BB * NCH * CC / 2) / 256, 256>>>(td);
    wkv_passB<<<(BB * CC / 2) / 256, 256>>>(td);
    wkv_passC<<<(BB * NCH * CC / 2) / 256, 256>>>(td, x);

    // LN2 -> x2 fp16 plane
    ln_kernel<<<BT, 256>>>(p_xmid, ln2_g, ln2_b, p_x2h);

    // join s2, then fused channel-mix: Wck (relu^2 -> Hh) + Wcr (sigmoid -> cr fp16)
    cudaStreamWaitEvent(0, evW2, 0);
    hmma_gemm_ck<<<dim3(80, BT / 128), 256, SMEM_BYTES>>>(p_x2h, p_Wckh, p_Wcrh, p_Hh, p_cr);

    // dv GEMM with fused final epilogue: out = xmid + cr * dv
    hmma_gemm<3><<<dim3(CC / 128, BT / 128), 256, SMEM_BYTES>>>(
        p_Hh, p_Wcvh, out, 0, p_xmid, p_cr, CC, FFD);
}

// round 16
// speedup vs baseline: 1.1451x; 1.0067x over previous
#include <cuda_runtime.h>
#include <cuda_fp16.h>
#include <cstdint>

#define BB 4
#define TT 2048
#define CC 2048
#define FFD 8192
#define BT (BB*TT)          // 8192
#define NCH 64
#define LCH 32

// ---------------- scratch (device globals; no allocation allowed) ----------
__device__ __half g_ek[(size_t)BT*CC];        // exp(k), computed in GEMM epilogue
__device__ __half g_v [(size_t)BT*CC];
__device__ __half g_r [(size_t)BT*CC];
__device__ __half g_xmid[(size_t)BT*CC];      // residual stream after WKV, fp16
__device__ __half g_cr [(size_t)BT*CC];       // sigmoid output, fp16
__device__ float g_Aloc[(size_t)BB*CC*NCH];
__device__ float g_Bloc[(size_t)BB*CC*NCH];
__device__ float g_Sa  [(size_t)BB*CC*NCH];
__device__ float g_Sb  [(size_t)BB*CC*NCH];

// fp16 planes
__device__ __half g_xph[((size_t)BT+1)*CC];   // padded: row0 = 0, row m+1 = xln row m
__device__ __half g_x2h[(size_t)BT*CC];
__device__ __half g_Hh [(size_t)BT*FFD];
__device__ __half g_Wqkv[(size_t)3*CC*CC];    // fused [Wk; Wv; Wr]
__device__ __half g_Wcrh[(size_t)CC*CC];
__device__ __half g_Wckh[(size_t)FFD*CC];
__device__ __half g_Wcvh[(size_t)CC*FFD];

// ======================= PTX helpers (compute_80-safe) ======================
__device__ __forceinline__ uint32_t smem_u32(const void* p) {
    uint32_t a;
    asm("{ .reg .u64 t; cvta.to.shared.u64 t, %1; cvt.u32.u64 %0, t; }" : "=r"(a) : "l"(p));
    return a;
}
__device__ __forceinline__ void cp_async16(uint32_t dst, const void* src) {
    asm volatile("cp.async.cg.shared.global [%0], [%1], 16;" :: "r"(dst), "l"(src) : "memory");
}
__device__ __forceinline__ void cp_commit() {
    asm volatile("cp.async.commit_group;" ::: "memory");
}
template <int N>
__device__ __forceinline__ void cp_wait() {
    asm volatile("cp.async.wait_group %0;" :: "n"(N) : "memory");
}
__device__ __forceinline__ void ldm_x4(uint32_t* r, uint32_t addr) {
    asm volatile("ldmatrix.sync.aligned.m8n8.x4.shared.b16 {%0,%1,%2,%3}, [%4];"
        : "=r"(r[0]), "=r"(r[1]), "=r"(r[2]), "=r"(r[3]) : "r"(addr));
}
__device__ __forceinline__ void mma_f16(float* d, const uint32_t* a, const uint32_t* b) {
    asm volatile(
        "mma.sync.aligned.m16n8k16.row.col.f32.f16.f16.f32 "
        "{%0,%1,%2,%3}, {%4,%5,%6,%7}, {%8,%9}, {%0,%1,%2,%3};"
        : "+f"(d[0]), "+f"(d[1]), "+f"(d[2]), "+f"(d[3])
        : "r"(a[0]), "r"(a[1]), "r"(a[2]), "r"(a[3]), "r"(b[0]), "r"(b[1]));
}
__device__ __forceinline__ uint32_t pkh(__half a, __half b) {
    return (uint32_t)__half_as_ushort(a) | ((uint32_t)__half_as_ushort(b) << 16);
}
// FMA-pipe reciprocal: bit-trick seed + 3 Newton steps (~1e-8 rel err).
__device__ __forceinline__ float fastrcp(float x) {
    float r = __uint_as_float(0x7EF311C3u - __float_as_uint(x));
    r = r * fmaf(-x, r, 2.0f);
    r = r * fmaf(-x, r, 2.0f);
    r = r * fmaf(-x, r, 2.0f);
    return r;
}

// ======================= HMMA GEMM core (round-13 mainloop) ==================
// Y[m0:m0+128, n0:n0+128] = A[128, K] @ W[128, K]^T  (Aptr/Wptr pre-offset).
// fp16 single plane, BK=32, 256 threads, 5-stage cp.async pipeline, 2 CTA/SM.
// EPI: 0 fp16 | 1 relu^2 fp16 | 2 sigmoid fp16 | 3 out = xadd(h) + xmul(h)*acc | 4 exp fp16
#define ROWB 80u
#define TILEB (128u*ROWB)         // 10240
#define STAGEB (2u*TILEB)         // 20480
#define NSTAGE 5
#define SMEM_BYTES (NSTAGE*STAGEB)  // 102400

template <int EPI>
__device__ __forceinline__ void gemm_core(
    const __half* __restrict__ Aptr, const __half* __restrict__ Wptr,
    float* __restrict__ out, __half* __restrict__ oh,
    const __half* __restrict__ xadd, const __half* __restrict__ xmul,
    int m0, int n0, int N, int K, char* smem)
{
    const uint32_t sbase = smem_u32(smem);
    const int tid  = threadIdx.x;
    const int lane = tid & 31;
    const int wid  = tid >> 5;
    const int warp_m = wid & 1;
    const int warp_n = wid >> 1;
    const int S = K >> 5;

    const __half* srcBase[2] = { Aptr, Wptr };

    auto load_stage = [&](int buf, int i) {
        const int k0 = i << 5;
        const uint32_t stage = sbase + buf * STAGEB;
        #pragma unroll
        for (int rep = 0; rep < 4; rep++) {
            const int idx = tid + rep * 256;
            const int tile = idx >> 9;
            const int r = (idx >> 2) & 127;
            const int s = idx & 3;
            const __half* src = srcBase[tile] + (size_t)r * K + k0 + s * 8;
            cp_async16(stage + tile * TILEB + r * ROWB + s * 16, src);
        }
    };

    #pragma unroll
    for (int p = 0; p < NSTAGE - 1; p++) { load_stage(p, p); cp_commit(); }

    float acc[4][4][4];
    #pragma unroll
    for (int mt = 0; mt < 4; mt++)
        #pragma unroll
        for (int nt = 0; nt < 4; nt++)
            #pragma unroll
            for (int q = 0; q < 4; q++) acc[mt][nt][q] = 0.f;

    const uint32_t aoff = (lane & 15) * ROWB + (lane >> 4) * 16;
    const uint32_t boff4 = ((lane >> 4) * 8 + (lane & 7)) * ROWB + ((lane >> 3) & 1) * 16;

    for (int i = 0; i < S; i++) {
        cp_wait<NSTAGE - 2>();
        __syncthreads();
        const uint32_t sb = sbase + (i % NSTAGE) * STAGEB;
        #pragma unroll
        for (int ks = 0; ks < 2; ks++) {
            const uint32_t kb = ks * 32;
            uint32_t ahf[4][4];
            #pragma unroll
            for (int mt = 0; mt < 4; mt++)
                ldm_x4(ahf[mt], sb + (warp_m * 64 + mt * 16) * ROWB + kb + aoff);
            uint32_t bhf[4][2];
            #pragma unroll
            for (int pair = 0; pair < 2; pair++) {
                uint32_t tmp[4];
                ldm_x4(tmp, sb + TILEB + (warp_n * 32 + pair * 16) * ROWB + kb + boff4);
                bhf[pair*2][0] = tmp[0]; bhf[pair*2][1] = tmp[1];
                bhf[pair*2+1][0] = tmp[2]; bhf[pair*2+1][1] = tmp[3];
            }
            #pragma unroll
            for (int mt = 0; mt < 4; mt++)
                #pragma unroll
                for (int nt = 0; nt < 4; nt++)
                    mma_f16(acc[mt][nt], ahf[mt], bhf[nt]);
        }
        if (i + NSTAGE - 1 < S) load_stage((i + NSTAGE - 1) % NSTAGE, i + NSTAGE - 1);
        cp_commit();
    }

    const int rbase = m0 + warp_m * 64 + (lane >> 2);
    const int cbase = n0 + warp_n * 32 + (lane & 3) * 2;
    #pragma unroll
    for (int mt = 0; mt < 4; mt++) {
        #pragma unroll
        for (int nt = 0; nt < 4; nt++) {
            const float* c = acc[mt][nt];
            const size_t r0 = (size_t)(rbase + mt * 16);
            const size_t r1 = r0 + 8;
            const int col = cbase + nt * 8;
            if (EPI == 0) {
                *(uint32_t*)&oh[r0 * N + col] = pkh(__float2half_rn(c[0]), __float2half_rn(c[1]));
                *(uint32_t*)&oh[r1 * N + col] = pkh(__float2half_rn(c[2]), __float2half_rn(c[3]));
            } else if (EPI == 4) {
                *(uint32_t*)&oh[r0 * N + col] = pkh(__float2half_rn(__expf(c[0])),
                                                    __float2half_rn(__expf(c[1])));
                *(uint32_t*)&oh[r1 * N + col] = pkh(__float2half_rn(__expf(c[2])),
                                                    __float2half_rn(__expf(c[3])));
            } else if (EPI == 2) {   // sigmoid -> fp16
                *(uint32_t*)&oh[r0 * N + col] = pkh(
                    __float2half_rn(1.f / (1.f + __expf(-c[0]))),
                    __float2half_rn(1.f / (1.f + __expf(-c[1]))));
                *(uint32_t*)&oh[r1 * N + col] = pkh(
                    __float2half_rn(1.f / (1.f + __expf(-c[2]))),
                    __float2half_rn(1.f / (1.f + __expf(-c[3]))));
            } else if (EPI == 3) {   // out = xadd(half) + xmul(half) * acc
                float2 a0 = __half22float2(*(const __half2*)&xadd[r0 * N + col]);
                float2 m0v = __half22float2(*(const __half2*)&xmul[r0 * N + col]);
                float2 a1 = __half22float2(*(const __half2*)&xadd[r1 * N + col]);
                float2 m1v = __half22float2(*(const __half2*)&xmul[r1 * N + col]);
                *(float2*)&out[r0 * N + col] = make_float2(
                    fmaf(m0v.x, c[0], a0.x), fmaf(m0v.y, c[1], a0.y));
                *(float2*)&out[r1 * N + col] = make_float2(
                    fmaf(m1v.x, c[2], a1.x), fmaf(m1v.y, c[3], a1.y));
            } else {   // EPI == 1: relu^2 -> fp16
                float f0 = c[0] > 0.f ? c[0] * c[0] : 0.f;
                float f1 = c[1] > 0.f ? c[1] * c[1] : 0.f;
                float f2 = c[2] > 0.f ? c[2] * c[2] : 0.f;
                float f3 = c[3] > 0.f ? c[3] * c[3] : 0.f;
                *(uint32_t*)&oh[r0 * N + col] = pkh(__float2half_rn(f0), __float2half_rn(f1));
                *(uint32_t*)&oh[r1 * N + col] = pkh(__float2half_rn(f2), __float2half_rn(f3));
            }
        }
    }
}

template <int EPI>
__global__ __launch_bounds__(256, 2) void hmma_gemm(
    const __half* __restrict__ Ah, const __half* __restrict__ Wh,
    float* __restrict__ out, __half* __restrict__ oh,
    const __half* __restrict__ xadd, const __half* __restrict__ xmul,
    int N, int K)
{
    extern __shared__ char smem[];
    const int m0 = blockIdx.y * 128;
    const int n0 = blockIdx.x * 128;
    gemm_core<EPI>(Ah + (size_t)m0 * K, Wh + (size_t)n0 * K,
                   out, oh, xadd, xmul, m0, n0, N, K, smem);
}

__global__ __launch_bounds__(256, 2) void hmma_gemm_qkv(
    const __half* __restrict__ xph, const __half* __restrict__ Wqkv,
    __half* __restrict__ outek, __half* __restrict__ outv, __half* __restrict__ outr)
{
    extern __shared__ char smem[];
    const int bx = blockIdx.x;
    const int region = bx >> 4;
    const int n0 = (bx & 15) * 128;
    const int m0 = blockIdx.y * 128;
    if (region == 0) {
        gemm_core<4>(xph + (size_t)m0 * CC, Wqkv + (size_t)bx * 128 * CC,
                     0, outek, 0, 0, m0, n0, CC, CC, smem);
    } else {
        const __half* A = (region == 1) ? xph : (xph + CC);
        __half* oh = (region == 1) ? outv : outr;
        gemm_core<0>(A + (size_t)m0 * CC, Wqkv + (size_t)bx * 128 * CC,
                     0, oh, 0, 0, m0, n0, CC, CC, smem);
    }
}

__global__ __launch_bounds__(256, 2) void hmma_gemm_ck(
    const __half* __restrict__ x2h,
    const __half* __restrict__ Wck, const __half* __restrict__ Wcr,
    __half* __restrict__ Hh, __half* __restrict__ cr)
{
    extern __shared__ char smem[];
    const int bx = blockIdx.x;
    const int m0 = blockIdx.y * 128;
    if (bx < 64) {
        gemm_core<1>(x2h + (size_t)m0 * CC, Wck + (size_t)bx * 128 * CC,
                     0, Hh, 0, 0, m0, bx * 128, FFD, CC, smem);
    } else {
        gemm_core<2>(x2h + (size_t)m0 * CC, Wcr + (size_t)(bx - 64) * 128 * CC,
                     0, cr, 0, 0, m0, (bx - 64) * 128, CC, CC, smem);
    }
}

// ======================= layernorm =========================================
__device__ __forceinline__ void blockReduce2(float& a, float& b) {
    __shared__ float sa[8], sb[8];
    int lane = threadIdx.x & 31, w = threadIdx.x >> 5;
    #pragma unroll
    for (int o = 16; o > 0; o >>= 1) {
        a += __shfl_down_sync(0xffffffffu, a, o);
        b += __shfl_down_sync(0xffffffffu, b, o);
    }
    if (lane == 0) { sa[w] = a; sb[w] = b; }
    __syncthreads();
    if (w == 0) {
        a = (lane < 8) ? sa[lane] : 0.f;
        b = (lane < 8) ? sb[lane] : 0.f;
        #pragma unroll
        for (int o = 4; o > 0; o >>= 1) {
            a += __shfl_down_sync(0xffffffffu, a, o);
            b += __shfl_down_sync(0xffffffffu, b, o);
        }
        if (lane == 0) { sa[0] = a; sb[0] = b; }
    }
    __syncthreads();
    a = sa[0]; b = sb[0];
    __syncthreads();
}

__global__ __launch_bounds__(256) void ln_kernel(
    const float* __restrict__ x, const float* __restrict__ g,
    const float* __restrict__ bia, __half* __restrict__ yh)
{
    size_t row = blockIdx.x;
    const float* xr = x + row * CC;
    float xv[8];
    float s = 0.f, q = 0.f;
    #pragma unroll
    for (int j = 0; j < 8; j++) {
        xv[j] = xr[threadIdx.x + 256 * j];
        s += xv[j]; q += xv[j] * xv[j];
    }
    blockReduce2(s, q);
    float mu = s * (1.f / CC);
    float var = q * (1.f / CC) - mu * mu;
    float rstd = rsqrtf(var + 1e-5f);
    #pragma unroll
    for (int j = 0; j < 8; j++) {
        int i = threadIdx.x + 256 * j;
        yh[row * CC + i] = __float2half_rn((xv[j] - mu) * rstd * g[i] + bia[i]);
    }
}

// LN over a half-precision input row (used for LN2 on fp16 xmid)
__global__ __launch_bounds__(256) void ln_kernel_h(
    const __half* __restrict__ x, const float* __restrict__ g,
    const float* __restrict__ bia, __half* __restrict__ yh)
{
    size_t row = blockIdx.x;
    const __half2* xr = (const __half2*)(x + row * CC);
    float2 xv[4];
    float s = 0.f, q = 0.f;
    #pragma unroll
    for (int j = 0; j < 4; j++) {
        xv[j] = __half22float2(xr[threadIdx.x + 256 * j]);
        s += xv[j].x + xv[j].y;
        q += xv[j].x * xv[j].x + xv[j].y * xv[j].y;
    }
    blockReduce2(s, q);
    float mu = s * (1.f / CC);
    float var = q * (1.f / CC) - mu * mu;
    float rstd = rsqrtf(var + 1e-5f);
    #pragma unroll
    for (int j = 0; j < 4; j++) {
        int i = (threadIdx.x + 256 * j) * 2;
        float y0 = (xv[j].x - mu) * rstd * g[i] + bia[i];
        float y1 = (xv[j].y - mu) * rstd * g[i + 1] + bia[i + 1];
        *(uint32_t*)&yh[row * CC + i] = pkh(__float2half_rn(y0), __float2half_rn(y1));
    }
}

__global__ __launch_bounds__(256) void state_ln_kernel(
    const float* __restrict__ x, const float* __restrict__ g,
    const float* __restrict__ bia, float* __restrict__ out)
{
    int b = blockIdx.x;
    const float* xr = x + ((size_t)b * TT + (TT - 2)) * CC;
    float s = 0.f, q = 0.f;
    for (int i = threadIdx.x; i < CC; i += 256) {
        float v = xr[i];
        s += v; q += v * v;
    }
    blockReduce2(s, q);
    float mu = s * (1.f / CC);
    float var = q * (1.f / CC) - mu * mu;
    float rstd = rsqrtf(var + 1e-5f);
    for (int i = threadIdx.x; i < CC; i += 256)
        out[(size_t)b * CC + i] = (xr[i] - mu) * rstd * g[i] + bia[i];
}

// ======================= converters / misc ==================================
__global__ __launch_bounds__(256) void conv_h(
    const float4* __restrict__ src, uint2* __restrict__ hi)
{
    size_t i = (size_t)blockIdx.x * 256 + threadIdx.x;
    float4 f = src[i];
    hi[i] = make_uint2(pkh(__float2half_rn(f.x), __float2half_rn(f.y)),
                       pkh(__float2half_rn(f.z), __float2half_rn(f.w)));
}

__global__ __launch_bounds__(256) void zero1(__half* a)
{
    int i = blockIdx.x * 256 + threadIdx.x;
    a[i] = __float2half_rn(0.f);
}

// ======================= WKV chunked scan (2-wide, ek precomputed) ==========
__global__ __launch_bounds__(256) void wkv_passA(const float* __restrict__ td)
{
    int tid = blockIdx.x * 256 + threadIdx.x;
    int c2 = tid % (CC/2);
    int j  = (tid / (CC/2)) % NCH;
    int b  = tid / ((CC/2) * NCH);
    float2 tdv = *(const float2*)&td[c2 * 2];
    float d0 = __expf(-__expf(tdv.x));
    float d1 = __expf(-__expf(tdv.y));
    float a0 = 0.f, a1 = 0.f, b0 = 0.f, b1 = 0.f;
    size_t base = ((size_t)b * TT + (size_t)j * LCH) * CC + c2 * 2;
    for (int t = 0; t < LCH; t++) {
        float2 ek = __half22float2(*(const __half2*)&g_ek[base + (size_t)t * CC]);
        float2 vv = __half22float2(*(const __half2*)&g_v [base + (size_t)t * CC]);
        if (j == 0 && t == 0) { ek = make_float2(1.f, 1.f); vv = make_float2(0.f, 0.f); }
        a0 = fmaf(d0, a0, ek.x * vv.x);
        a1 = fmaf(d1, a1, ek.y * vv.y);
        b0 = fmaf(d0, b0, ek.x);
        b1 = fmaf(d1, b1, ek.y);
    }
    size_t idx = ((size_t)b * NCH + j) * CC + c2 * 2;
    *(float2*)&g_Aloc[idx] = make_float2(a0, a1);
    *(float2*)&g_Bloc[idx] = make_float2(b0, b1);
}

__global__ __launch_bounds__(256) void wkv_passB(const float* __restrict__ td)
{
    int tid = blockIdx.x * 256 + threadIdx.x;    // BB*CC/2 threads
    int c2 = tid % (CC/2);
    int b  = tid / (CC/2);
    float2 tdv = *(const float2*)&td[c2 * 2];
    float dL0 = __expf(-(float)LCH * __expf(tdv.x));
    float dL1 = __expf(-(float)LCH * __expf(tdv.y));
    float sa0 = 0.f, sa1 = 0.f, sb0 = 0.f, sb1 = 0.f;
    for (int j = 0; j < NCH; j++) {
        size_t idx = ((size_t)b * NCH + j) * CC + c2 * 2;
        *(float2*)&g_Sa[idx] = make_float2(sa0, sa1);
        *(float2*)&g_Sb[idx] = make_float2(sb0, sb1);
        float2 al = *(const float2*)&g_Aloc[idx];
        float2 bl = *(const float2*)&g_Bloc[idx];
        sa0 = fmaf(dL0, sa0, al.x);
        sa1 = fmaf(dL1, sa1, al.y);
        sb0 = fmaf(dL0, sb0, bl.x);
        sb1 = fmaf(dL1, sb1, bl.y);
    }
}

__global__ __launch_bounds__(256) void wkv_passC(
    const float* __restrict__ td, const float* __restrict__ x)
{
    int tid = blockIdx.x * 256 + threadIdx.x;
    int c2 = tid % (CC/2);
    int j  = (tid / (CC/2)) % NCH;
    int b  = tid / ((CC/2) * NCH);
    float2 tdv = *(const float2*)&td[c2 * 2];
    float d0 = __expf(-__expf(tdv.x));
    float d1 = __expf(-__expf(tdv.y));
    size_t idx = ((size_t)b * NCH + j) * CC + c2 * 2;
    float2 sa = *(const float2*)&g_Sa[idx];
    float2 sb = *(const float2*)&g_Sb[idx];
    float a0 = sa.x, a1 = sa.y, b0 = sb.x, b1 = sb.y;
    size_t base = ((size_t)b * TT + (size_t)j * LCH) * CC + c2 * 2;
    for (int t = 0; t < LCH; t++) {
        size_t p = base + (size_t)t * CC;
        float2 ek = __half22float2(*(const __half2*)&g_ek[p]);
        float2 vv = __half22float2(*(const __half2*)&g_v [p]);
        if (j == 0 && t == 0) { ek = make_float2(1.f, 1.f); vv = make_float2(0.f, 0.f); }
        a0 = fmaf(d0, a0, ek.x * vv.x);
        a1 = fmaf(d1, a1, ek.y * vv.y);
        b0 = fmaf(d0, b0, ek.x);
        b1 = fmaf(d1, b1, ek.y);
        float2 rr = __half22float2(*(const __half2*)&g_r[p]);
        float2 xx = *(const float2*)&x[p];
        float w0 = a0 * fastrcp(b0 + 1e-8f);
        float w1 = a1 * fastrcp(b1 + 1e-8f);
        *(uint32_t*)&g_xmid[p] = pkh(
            __float2half_rn(fmaf(rr.x, w0, xx.x)),
            __float2half_rn(fmaf(rr.y, w1, xx.y)));
    }
}

// ======================= host launch =========================================
extern "C" void kernel_launch(void* const* d_in, const int* in_sizes, int n_in,
                              void* d_out, int out_size)
{
    const float* x     = (const float*)d_in[0];
    const float* ln1_g = (const float*)d_in[1];
    const float* ln1_b = (const float*)d_in[2];
    const float* td    = (const float*)d_in[3];
    const float* Wk    = (const float*)d_in[4];
    const float* Wv    = (const float*)d_in[5];
    const float* Wr    = (const float*)d_in[6];
    const float* ln2_g = (const float*)d_in[7];
    const float* ln2_b = (const float*)d_in[8];
    const float* Wck   = (const float*)d_in[9];
    const float* Wcv   = (const float*)d_in[10];
    const float* Wcr   = (const float*)d_in[11];
    float* out = (float*)d_out;

    __half *p_ek, *p_v, *p_r, *p_xmid, *p_cr;
    __half *p_xph, *p_x2h, *p_Hh, *p_Wqkv, *p_Wcrh, *p_Wckh, *p_Wcvh;
    cudaGetSymbolAddress((void**)&p_ek,   g_ek);
    cudaGetSymbolAddress((void**)&p_v,    g_v);
    cudaGetSymbolAddress((void**)&p_r,    g_r);
    cudaGetSymbolAddress((void**)&p_xmid, g_xmid);
    cudaGetSymbolAddress((void**)&p_cr,   g_cr);
    cudaGetSymbolAddress((void**)&p_xph,  g_xph);
    cudaGetSymbolAddress((void**)&p_x2h,  g_x2h);
    cudaGetSymbolAddress((void**)&p_Hh,   g_Hh);
    cudaGetSymbolAddress((void**)&p_Wqkv, g_Wqkv);
    cudaGetSymbolAddress((void**)&p_Wcrh, g_Wcrh);
    cudaGetSymbolAddress((void**)&p_Wckh, g_Wckh);
    cudaGetSymbolAddress((void**)&p_Wcvh, g_Wcvh);

    cudaFuncSetAttribute(hmma_gemm<3>,  cudaFuncAttributeMaxDynamicSharedMemorySize, SMEM_BYTES);
    cudaFuncSetAttribute(hmma_gemm_qkv, cudaFuncAttributeMaxDynamicSharedMemorySize, SMEM_BYTES);
    cudaFuncSetAttribute(hmma_gemm_ck,  cudaFuncAttributeMaxDynamicSharedMemorySize, SMEM_BYTES);

    // fork-join side streams (created once; host-side objects, no device memory)
    static cudaStream_t s1 = nullptr, s2 = nullptr;
    static cudaEvent_t evRoot = nullptr, evQKVW = nullptr, evW2 = nullptr;
    if (!s1) {
        cudaStreamCreateWithFlags(&s1, cudaStreamNonBlocking);
        cudaStreamCreateWithFlags(&s2, cudaStreamNonBlocking);
        cudaEventCreateWithFlags(&evRoot, cudaEventDisableTiming);
        cudaEventCreateWithFlags(&evQKVW, cudaEventDisableTiming);
        cudaEventCreateWithFlags(&evW2,   cudaEventDisableTiming);
    }

    // ---- fork ----
    cudaEventRecord(evRoot, 0);
    cudaStreamWaitEvent(s1, evRoot, 0);
    cudaStreamWaitEvent(s2, evRoot, 0);

    // s1: qkv weight conversion (parallel with LN1/zero on s0)
    conv_h<<<(CC*CC)/1024, 256, 0, s1>>>((const float4*)Wk, (uint2*)p_Wqkv);
    conv_h<<<(CC*CC)/1024, 256, 0, s1>>>((const float4*)Wv, (uint2*)(p_Wqkv + (size_t)CC*CC));
    conv_h<<<(CC*CC)/1024, 256, 0, s1>>>((const float4*)Wr, (uint2*)(p_Wqkv + (size_t)2*CC*CC));
    cudaEventRecord(evQKVW, s1);

    // s2: channel-mix weight conversions + state output (parallel with qkv GEMM on s0)
    conv_h<<<(CC*CC)/1024,  256, 0, s2>>>((const float4*)Wcr, (uint2*)p_Wcrh);
    conv_h<<<(FFD*CC)/1024, 256, 0, s2>>>((const float4*)Wck, (uint2*)p_Wckh);
    conv_h<<<(CC*FFD)/1024, 256, 0, s2>>>((const float4*)Wcv, (uint2*)p_Wcvh);
    if ((size_t)out_size >= (size_t)BT * CC + (size_t)BB * CC)
        state_ln_kernel<<<BB, 256, 0, s2>>>(x, ln1_g, ln1_b, out + (size_t)BT * CC);
    cudaEventRecord(evW2, s2);

    // s0: LN1 -> padded fp16 plane (row m at plane row m+1), zero row 0
    ln_kernel<<<BT, 256>>>(x, ln1_g, ln1_b, p_xph + CC);
    zero1<<<CC/256, 256>>>(p_xph);

    // join s1, then fused k/v/r GEMM (k region stores exp(k))
    cudaStreamWaitEvent(0, evQKVW, 0);
    hmma_gemm_qkv<<<dim3(48, BT / 128), 256, SMEM_BYTES>>>(p_xph, p_Wqkv, p_ek, p_v, p_r);

    // WKV scan + residual -> xmid fp16 (2-wide kernels)
    wkv_passA<<<(BB * NCH * CC / 2) / 256, 256>>>(td);
    wkv_passB<<<(BB * CC / 2) / 256, 256>>>(td);
    wkv_passC<<<(BB * NCH * CC / 2) / 256, 256>>>(td, x);

    // LN2 (fp16 input) -> x2 fp16 plane
    ln_kernel_h<<<BT, 256>>>(p_xmid, ln2_g, ln2_b, p_x2h);

    // join s2, then fused channel-mix: Wck (relu^2 -> Hh) + Wcr (sigmoid -> cr fp16)
    cudaStreamWaitEvent(0, evW2, 0);
    hmma_gemm_ck<<<dim3(80, BT / 128), 256, SMEM_BYTES>>>(p_x2h, p_Wckh, p_Wcrh, p_Hh, p_cr);

    // dv GEMM with fused final epilogue: out = xmid(h) + cr(h) * dv
    hmma_gemm<3><<<dim3(CC / 128, BT / 128), 256, SMEM_BYTES>>>(
        p_Hh, p_Wcvh, out, 0, p_xmid, p_cr, CC, FFD);
}